// round 1
// baseline (speedup 1.0000x reference)
#include <cuda_runtime.h>

// Problem constants (fixed by setup_inputs)
#define B_   16
#define L_   128
#define N_   (B_*L_)      // 2048
#define C_   14
#define E_   256
#define K_   9
#define BIGF 1e10f

// Output layout (float32, outputs flattened + concatenated in reference order)
#define OFF_H          0u
#define OFF_CTX_KNN    1048576u
#define OFF_CTX_VALID  1085440u
#define OFF_ADJ        1103872u
#define OFF_INT_KNN    1366016u
#define OFF_INT_VALID  1402880u
#define KNN_ROWS       (N_*K_)   // 18432

static __device__ float g_dist[B_ * L_ * L_];   // 1 MB scratch

__device__ __forceinline__ bool is_glob(int s) { return (s == 21) | (s == 22) | (s == 23); }

// ---------------------------------------------------------------------------
// 1) Embedding: h[n, 0:256] = res_embed[S[n]] + sinusoid(RP[n])
//    h[n, 256:512] = masked mean over atoms of atom_embed[A] + atom_pos_embed[AP]
// ---------------------------------------------------------------------------
__global__ void embed_kernel(const int* __restrict__ S, const int* __restrict__ RP,
                             const int* __restrict__ A, const int* __restrict__ AP,
                             const float* __restrict__ res_e,
                             const float* __restrict__ atom_e,
                             const float* __restrict__ atom_pe,
                             float* __restrict__ out)
{
    int n = blockIdx.x;          // residue 0..2047
    int e = threadIdx.x;         // channel 0..255
    __shared__ int sA[C_], sAP[C_];
    __shared__ float sden;
    if (e < C_) { sA[e] = A[n*C_ + e]; sAP[e] = AP[n*C_ + e]; }
    __syncthreads();
    if (e == 0) {
        int cnt = 0;
        #pragma unroll
        for (int c = 0; c < C_; c++) cnt += (sAP[c] != 0);
        sden = (float)cnt + 1e-10f;
    }
    __syncthreads();

    // residue + positional part
    int   s   = S[n];
    float rp  = (float)RP[n];
    int   i   = e >> 1;
    float inv = powf(10000.0f, -(float)i * (1.0f / 128.0f));
    float ang = rp * inv;
    float pos = (e & 1) ? cosf(ang) : sinf(ang);
    out[OFF_H + (unsigned)n * 512u + e] = res_e[s * E_ + e] + pos;

    // atom part
    float acc = 0.0f;
    #pragma unroll
    for (int c = 0; c < C_; c++) {
        int ap = sAP[c];
        if (ap != 0) acc += atom_e[sA[c] * E_ + e] + atom_pe[ap * E_ + e];
    }
    out[OFF_H + (unsigned)n * 512u + 256u + e] = acc / sden;
}

// ---------------------------------------------------------------------------
// 2) Min pairwise atom distance per residue pair. Block = (b,i), thread = j.
//    dist[b,i,j] = sqrt(max(min over valid atom pairs of (sq_i + sq_j - 2 dot), 0))
// ---------------------------------------------------------------------------
__global__ void dist_kernel(const float* __restrict__ X, const int* __restrict__ AP,
                            float* __restrict__ dist)
{
    int bi = blockIdx.x;           // b*128 + i
    int b  = bi >> 7;
    int t  = threadIdx.x;          // j in 0..127

    __shared__ float xi0[C_], xi1[C_], xi2[C_], sqi[C_];
    __shared__ int maski;
    if (t < C_) {
        float x0 = X[(bi*C_ + t)*3 + 0];
        float x1 = X[(bi*C_ + t)*3 + 1];
        float x2 = X[(bi*C_ + t)*3 + 2];
        xi0[t] = x0; xi1[t] = x1; xi2[t] = x2;
        sqi[t] = (x0*x0 + x1*x1) + x2*x2;
    }
    if (t == 0) {
        int m = 0;
        #pragma unroll
        for (int c = 0; c < C_; c++) m |= (AP[bi*C_ + c] != 0) ? (1 << c) : 0;
        maski = m;
    }
    __syncthreads();

    int nj = b * L_ + t;
    int mi = maski;
    float best = 3.0e38f;
    #pragma unroll
    for (int cp = 0; cp < C_; cp++) {
        if (AP[nj*C_ + cp] == 0) continue;
        float y0 = X[(nj*C_ + cp)*3 + 0];
        float y1 = X[(nj*C_ + cp)*3 + 1];
        float y2 = X[(nj*C_ + cp)*3 + 2];
        float sj = (y0*y0 + y1*y1) + y2*y2;
        #pragma unroll
        for (int c = 0; c < C_; c++) {
            if (!((mi >> c) & 1)) continue;
            float dot = (xi0[c]*y0 + xi1[c]*y1) + xi2[c]*y2;
            float d2  = (sqi[c] + sj) - 2.0f * dot;
            best = fminf(best, d2);
        }
    }
    dist[bi * L_ + t] = sqrtf(fmaxf(best, 0.0f));
}

// ---------------------------------------------------------------------------
// 3) KNN: one warp per (row, type). type 0 = inner (ctx), type 1 = outer (inter).
//    Reproduces jax.lax.top_k(-d) tie-breaking (smaller index wins on equal d).
// ---------------------------------------------------------------------------
__global__ void knn_kernel(const int* __restrict__ S, const int* __restrict__ seg,
                           const float* __restrict__ dist, float* __restrict__ out)
{
    int w    = blockIdx.x * 4 + (threadIdx.x >> 5);   // 0..4095
    int lane = threadIdx.x & 31;
    int type = w & 1;
    int r    = w >> 1;                                 // row 0..2047
    int b    = r >> 7;
    int i    = r & 127;

    int  si = seg[r];
    bool gi = is_glob(S[r]);

    float v[4];
    #pragma unroll
    for (int s2 = 0; s2 < 4; s2++) {
        int j  = lane + 32 * s2;
        int nj = b * L_ + j;
        bool gj   = is_glob(S[nj]);
        bool same = (seg[nj] == si);
        bool m;
        if (type == 0) m = same && !gi && !gj && (j != i);
        else           m = !same && !gi && !gj;
        v[s2] = m ? dist[r * L_ + j] : BIGF;
    }

    unsigned offK = type ? OFF_INT_KNN   : OFF_CTX_KNN;
    unsigned offV = type ? OFF_INT_VALID : OFF_CTX_VALID;

    for (int k = 0; k < K_; k++) {
        // lane-local best (value, index) with smaller-index tiebreak
        float bv = v[0]; int bj = lane;
        #pragma unroll
        for (int s2 = 1; s2 < 4; s2++) {
            int j = lane + 32 * s2;
            if (v[s2] < bv) { bv = v[s2]; bj = j; }   // j increases with s2, so '<' suffices
        }
        // warp butterfly arg-min (lexicographic by (value, index))
        #pragma unroll
        for (int off = 16; off; off >>= 1) {
            float ov = __shfl_xor_sync(0xffffffffu, bv, off);
            int   oj = __shfl_xor_sync(0xffffffffu, bj, off);
            if (ov < bv || (ov == bv && oj < bj)) { bv = ov; bj = oj; }
        }
        // remove winner from owner lane
        if (lane == (bj & 31)) v[bj >> 5] = 3.0e38f;
        if (lane == 0) {
            bool valid = bv < BIGF;
            out[offK + (unsigned)r * K_ + k]            = valid ? (float)r            : -1.0f;
            out[offK + KNN_ROWS + (unsigned)r * K_ + k] = valid ? (float)(b*L_ + bj)  : -1.0f;
            out[offV + (unsigned)r * K_ + k]            = valid ? 1.0f : 0.0f;
        }
    }
}

// ---------------------------------------------------------------------------
// 4) extra_ctx_adj boolean matrix
// ---------------------------------------------------------------------------
__global__ void adj_kernel(const int* __restrict__ S, const int* __restrict__ seg,
                           float* __restrict__ out)
{
    int idx = blockIdx.x * 256 + threadIdx.x;     // < 262144
    int j = idx & 127;
    int i = (idx >> 7) & 127;
    int b = idx >> 14;
    int ni = b * L_ + i, nj = b * L_ + j;
    bool gi = is_glob(S[ni]);
    bool gj = is_glob(S[nj]);
    bool same = (seg[ni] == seg[nj]);
    bool ns   = (i != j);
    bool gn = same && (gi || gj) && ns;
    bool gg = gi && gj && ns;
    int  d  = i - j; if (d < 0) d = -d;
    bool sm = (d == 1) && !gi && !gj && (seg[ni] != 1);
    out[OFF_ADJ + (unsigned)idx] = (gn || gg || sm) ? 1.0f : 0.0f;
}

// ---------------------------------------------------------------------------
extern "C" void kernel_launch(void* const* d_in, const int* in_sizes, int n_in,
                              void* d_out, int out_size)
{
    const int*   S   = (const int*)  d_in[0];
    const int*   RP  = (const int*)  d_in[1];
    const int*   A   = (const int*)  d_in[2];
    const int*   AP  = (const int*)  d_in[3];
    const float* X   = (const float*)d_in[4];
    const int*   seg = (const int*)  d_in[5];
    const float* re  = (const float*)d_in[6];
    const float* ae  = (const float*)d_in[7];
    const float* ape = (const float*)d_in[8];
    float* out = (float*)d_out;

    float* dist = g_dist;

    embed_kernel<<<N_, E_>>>(S, RP, A, AP, re, ae, ape, out);
    dist_kernel <<<N_, L_>>>(X, AP, dist);
    knn_kernel  <<<N_ * 2 / 4, 128>>>(S, seg, dist, out);
    adj_kernel  <<<(B_*L_*L_) / 256, 256>>>(S, seg, out);
}

// round 2
// speedup vs baseline: 1.7513x; 1.7513x over previous
#include <cuda_runtime.h>
#include <float.h>

// Problem constants (fixed by setup_inputs)
#define B_   16
#define L_   128
#define N_   (B_*L_)      // 2048
#define C_   14
#define E_   256
#define K_   9
#define TI_  4            // i-rows per block in fused kernel
#define BIGF 1e10f
#define POISON 3.0e38f

// Output layout (float32, outputs flattened + concatenated in reference order)
#define OFF_H          0u
#define OFF_CTX_KNN    1048576u
#define OFF_CTX_VALID  1085440u
#define OFF_ADJ        1103872u
#define OFF_INT_KNN    1366016u
#define OFF_INT_VALID  1402880u
#define KNN_ROWS       (N_*K_)   // 18432

__device__ __forceinline__ bool is_glob(int s) { return (s == 21) | (s == 22) | (s == 23); }

// ---------------------------------------------------------------------------
// 1) Embedding: h[n, 0:256] = res_embed[S[n]] + sinusoid(RP[n])
//    h[n, 256:512] = masked mean over atoms of atom_embed[A] + atom_pos_embed[AP]
// ---------------------------------------------------------------------------
__global__ void embed_kernel(const int* __restrict__ S, const int* __restrict__ RP,
                             const int* __restrict__ A, const int* __restrict__ AP,
                             const float* __restrict__ res_e,
                             const float* __restrict__ atom_e,
                             const float* __restrict__ atom_pe,
                             float* __restrict__ out)
{
    int n = blockIdx.x;          // residue 0..2047
    int e = threadIdx.x;         // channel 0..255
    __shared__ int sA[C_], sAP[C_];
    __shared__ float sden;
    if (e < C_) { sA[e] = A[n*C_ + e]; sAP[e] = AP[n*C_ + e]; }
    __syncthreads();
    if (e == 0) {
        int cnt = 0;
        #pragma unroll
        for (int c = 0; c < C_; c++) cnt += (sAP[c] != 0);
        sden = (float)cnt + 1e-10f;
    }
    __syncthreads();

    // residue + positional part:  inv = 10000^(-i/128) = 2^(-i * log2(1e4)/128)
    int   s   = S[n];
    float rp  = (float)RP[n];
    int   i   = e >> 1;
    float inv = exp2f(-(float)i * (13.287712379549449f / 128.0f));
    float ang = rp * inv;
    float pos = (e & 1) ? cosf(ang) : sinf(ang);
    out[OFF_H + (unsigned)n * 512u + e] = res_e[s * E_ + e] + pos;

    // atom part
    float acc = 0.0f;
    #pragma unroll
    for (int c = 0; c < C_; c++) {
        int ap = sAP[c];
        if (ap != 0) acc += atom_e[sA[c] * E_ + e] + atom_pe[ap * E_ + e];
    }
    out[OFF_H + (unsigned)n * 512u + 256u + e] = acc / sden;
}

// ---------------------------------------------------------------------------
// 2) Fused dist + knn + adj.
//    Block = (b, tile of TI_ consecutive i rows), 128 threads (thread t = column j).
//    - Stage batch atom coords via padded smem transpose (coalesced LDG).
//    - Poison invalid atoms' squared norms -> branch-free inner loop.
//    - 4 warps run 2*TI_ warp-level top-k tasks on the smem dist rows.
// ---------------------------------------------------------------------------
__global__ void __launch_bounds__(L_) fused_kernel(
        const float* __restrict__ X, const int* __restrict__ AP,
        const int* __restrict__ S, const int* __restrict__ seg,
        float* __restrict__ out)
{
    const int b  = blockIdx.x >> 5;          // 32 tiles per batch (128/TI_)
    const int i0 = (blockIdx.x & 31) * TI_;
    const int t  = threadIdx.x;              // j column 0..127
    const int lane = t & 31;
    const int wid  = t >> 5;

    __shared__ float sraw[42 * 129];         // [r=c*3+d][j], pitch 129 (transpose pad)
    __shared__ float ssq [C_ * L_];          // [c][j], poisoned if atom invalid
    __shared__ float sdist[TI_ * L_];        // dist rows for this tile
    __shared__ int   sS[L_], sSeg[L_];

    // --- load phase: coalesced read of the whole batch's coords (5376 floats) ---
    const float* Xb = X + (size_t)b * L_ * C_ * 3;
    #pragma unroll
    for (int k = 0; k < 42; k++) {
        int idx = k * L_ + t;                // global offset within batch
        int j   = idx / 42;
        int r   = idx - j * 42;
        sraw[r * 129 + j] = Xb[idx];
    }
    sS[t]   = S[b * L_ + t];
    sSeg[t] = seg[b * L_ + t];
    __syncthreads();

    // --- per-column: own coords + squared norms into registers, poisoned sq to smem ---
    float y0[C_], y1[C_], y2[C_], sj[C_];
    const int* apRow = AP + ((size_t)b * L_ + t) * C_;
    #pragma unroll
    for (int c = 0; c < C_; c++) {
        float a0 = sraw[(3*c + 0) * 129 + t];
        float a1 = sraw[(3*c + 1) * 129 + t];
        float a2 = sraw[(3*c + 2) * 129 + t];
        y0[c] = a0; y1[c] = a1; y2[c] = a2;
        float sq = (a0*a0 + a1*a1) + a2*a2;
        sq = (apRow[c] != 0) ? sq : POISON;
        sj[c] = sq;
        ssq[c * L_ + t] = sq;
    }
    __syncthreads();

    // --- distance rows: thread t computes dist[i][t] for the TI_ rows ---
    #pragma unroll
    for (int ii = 0; ii < TI_; ii++) {
        int i = i0 + ii;
        float best0 = FLT_MAX, best1 = FLT_MAX;
        #pragma unroll 2
        for (int c = 0; c < C_; c++) {
            float xi0 = sraw[(3*c + 0) * 129 + i];   // broadcast
            float xi1 = sraw[(3*c + 1) * 129 + i];
            float xi2 = sraw[(3*c + 2) * 129 + i];
            float sqc = ssq[c * L_ + i];
            #pragma unroll
            for (int cp = 0; cp < C_; cp += 2) {
                {
                    float dot = (xi0*y0[cp] + xi1*y1[cp]) + xi2*y2[cp];
                    best0 = fminf(best0, (sqc + sj[cp]) - 2.0f * dot);
                }
                {
                    float dot = (xi0*y0[cp+1] + xi1*y1[cp+1]) + xi2*y2[cp+1];
                    best1 = fminf(best1, (sqc + sj[cp+1]) - 2.0f * dot);
                }
            }
        }
        float best = fminf(best0, best1);
        sdist[ii * L_ + t] = sqrtf(fmaxf(best, 0.0f));
    }

    // --- adj rows (independent of sdist; only needs sS/sSeg) ---
    {
        bool gj = is_glob(sS[t]);
        int  segj = sSeg[t];
        #pragma unroll
        for (int ii = 0; ii < TI_; ii++) {
            int i = i0 + ii;
            bool gi = is_glob(sS[i]);
            bool same = (sSeg[i] == segj);
            bool ns   = (i != t);
            bool gn = same && (gi || gj) && ns;
            bool gg = gi && gj && ns;
            int  d  = i - t; if (d < 0) d = -d;
            bool sm = (d == 1) && !gi && !gj && (sSeg[i] != 1);
            out[OFF_ADJ + ((unsigned)(b * L_ + i)) * L_ + t] = (gn || gg || sm) ? 1.0f : 0.0f;
        }
    }
    __syncthreads();

    // --- knn: 2*TI_ warp tasks over the smem dist rows ---
    for (int tt = wid; tt < 2 * TI_; tt += 4) {
        int ii   = tt >> 1;
        int type = tt & 1;                  // 0 = ctx (inner), 1 = inter (outer)
        int i    = i0 + ii;
        int r    = b * L_ + i;
        bool gi  = is_glob(sS[i]);
        int  si  = sSeg[i];

        float v[4];
        #pragma unroll
        for (int s2 = 0; s2 < 4; s2++) {
            int j = lane + 32 * s2;
            bool gj   = is_glob(sS[j]);
            bool same = (sSeg[j] == si);
            bool m;
            if (type == 0) m = same && !gi && !gj && (j != i);
            else           m = !same && !gi && !gj;
            v[s2] = m ? sdist[ii * L_ + j] : BIGF;
        }

        unsigned offK = type ? OFF_INT_KNN   : OFF_CTX_KNN;
        unsigned offV = type ? OFF_INT_VALID : OFF_CTX_VALID;

        for (int k = 0; k < K_; k++) {
            float bv = v[0]; int bj = lane;
            #pragma unroll
            for (int s2 = 1; s2 < 4; s2++) {
                int j = lane + 32 * s2;
                if (v[s2] < bv) { bv = v[s2]; bj = j; }  // j increases, '<' keeps smallest index
            }
            #pragma unroll
            for (int off = 16; off; off >>= 1) {
                float ov = __shfl_xor_sync(0xffffffffu, bv, off);
                int   oj = __shfl_xor_sync(0xffffffffu, bj, off);
                if (ov < bv || (ov == bv && oj < bj)) { bv = ov; bj = oj; }
            }
            if (lane == (bj & 31)) v[bj >> 5] = POISON;
            if (lane == 0) {
                bool valid = bv < BIGF;
                out[offK + (unsigned)r * K_ + k]            = valid ? (float)r           : -1.0f;
                out[offK + KNN_ROWS + (unsigned)r * K_ + k] = valid ? (float)(b*L_ + bj) : -1.0f;
                out[offV + (unsigned)r * K_ + k]            = valid ? 1.0f : 0.0f;
            }
        }
    }
}

// ---------------------------------------------------------------------------
extern "C" void kernel_launch(void* const* d_in, const int* in_sizes, int n_in,
                              void* d_out, int out_size)
{
    const int*   S   = (const int*)  d_in[0];
    const int*   RP  = (const int*)  d_in[1];
    const int*   A   = (const int*)  d_in[2];
    const int*   AP  = (const int*)  d_in[3];
    const float* X   = (const float*)d_in[4];
    const int*   seg = (const int*)  d_in[5];
    const float* re  = (const float*)d_in[6];
    const float* ae  = (const float*)d_in[7];
    const float* ape = (const float*)d_in[8];
    float* out = (float*)d_out;

    embed_kernel<<<N_, E_>>>(S, RP, A, AP, re, ae, ape, out);
    fused_kernel<<<B_ * (L_ / TI_), L_>>>(X, AP, S, seg, out);
}

// round 3
// speedup vs baseline: 2.1610x; 1.2339x over previous
#include <cuda_runtime.h>
#include <float.h>

// Problem constants (fixed by setup_inputs)
#define B_   16
#define L_   128
#define N_   (B_*L_)      // 2048
#define C_   14
#define E_   256
#define K_   9
#define TI_  2            // i-rows per fused block
#define FUSED_BLOCKS (B_ * (L_ / TI_))   // 1024
#define BIGF 1e10f
#define POISON 3.0e38f

// Output layout (float32, outputs flattened + concatenated in reference order)
#define OFF_H          0u
#define OFF_CTX_KNN    1048576u
#define OFF_CTX_VALID  1085440u
#define OFF_ADJ        1103872u
#define OFF_INT_KNN    1366016u
#define OFF_INT_VALID  1402880u
#define KNN_ROWS       (N_*K_)   // 18432

__device__ __forceinline__ bool is_glob(int s) { return (s == 21) | (s == 22) | (s == 23); }

// ---- packed f32x2 helpers (sm_103a FFMA2 path; per-half IEEE identical to scalar) ----
typedef unsigned long long u64t;
__device__ __forceinline__ u64t pack2(float lo, float hi) {
    u64t r; asm("mov.b64 %0, {%1,%2};" : "=l"(r) : "f"(lo), "f"(hi)); return r;
}
__device__ __forceinline__ void unpack2(u64t p, float& lo, float& hi) {
    asm("mov.b64 {%0,%1}, %2;" : "=f"(lo), "=f"(hi) : "l"(p));
}
__device__ __forceinline__ u64t mul2(u64t a, u64t b) {
    u64t r; asm("mul.rn.f32x2 %0, %1, %2;" : "=l"(r) : "l"(a), "l"(b)); return r;
}
__device__ __forceinline__ u64t add2(u64t a, u64t b) {
    u64t r; asm("add.rn.f32x2 %0, %1, %2;" : "=l"(r) : "l"(a), "l"(b)); return r;
}
__device__ __forceinline__ u64t fma2(u64t a, u64t b, u64t c) {
    u64t r; asm("fma.rn.f32x2 %0, %1, %2, %3;" : "=l"(r) : "l"(a), "l"(b), "l"(c)); return r;
}

// Shared memory carve (max of both branches; fused dominates)
struct SmemFused {
    float sraw[42 * 129];     // [r=c*3+d][j], pitch 129 (transpose pad)
    float ssq [C_ * L_];      // [c][j], poisoned if atom invalid
    float sdist[TI_ * L_];
    int   sS[L_], sSeg[L_];
};
struct SmemEmbed {
    int sA[C_], sAP[C_];
};
union SmemAll { SmemFused f; SmemEmbed e; };

// ---------------------------------------------------------------------------
// Single kernel; blockIdx < FUSED_BLOCKS -> dist+knn+adj, else -> embed.
// ---------------------------------------------------------------------------
__global__ void __launch_bounds__(L_) mono_kernel(
        const float* __restrict__ X, const int* __restrict__ AP,
        const int* __restrict__ S, const int* __restrict__ seg,
        const int* __restrict__ RP, const int* __restrict__ A,
        const float* __restrict__ res_e, const float* __restrict__ atom_e,
        const float* __restrict__ atom_pe,
        float* __restrict__ out)
{
    __shared__ SmemAll sm;
    const int t = threadIdx.x;

    if (blockIdx.x >= FUSED_BLOCKS) {
        // ================= EMBED: one residue, 128 threads x 2 channels =====
        const int n = blockIdx.x - FUSED_BLOCKS;
        if (t < C_) { sm.e.sA[t] = A[n*C_ + t]; sm.e.sAP[t] = AP[n*C_ + t]; }
        __syncthreads();
        int cnt = 0;
        #pragma unroll
        for (int c = 0; c < C_; c++) cnt += (sm.e.sAP[c] != 0);
        float den = (float)cnt + 1e-10f;

        int   s  = S[n];
        float rp = (float)RP[n];
        #pragma unroll
        for (int e = t; e < E_; e += L_) {
            int   i   = e >> 1;
            float inv = exp2f(-(float)i * (13.287712379549449f / 128.0f));
            float ang = rp * inv;
            float pos = (e & 1) ? cosf(ang) : sinf(ang);
            out[OFF_H + (unsigned)n * 512u + e] = res_e[s * E_ + e] + pos;

            float acc = 0.0f;
            #pragma unroll
            for (int c = 0; c < C_; c++) {
                int ap = sm.e.sAP[c];
                if (ap != 0) acc += atom_e[sm.e.sA[c] * E_ + e] + atom_pe[ap * E_ + e];
            }
            out[OFF_H + (unsigned)n * 512u + 256u + e] = acc / den;
        }
        return;
    }

    // ================= FUSED dist + knn + adj ===============================
    const int b  = blockIdx.x / (L_ / TI_);
    const int i0 = (blockIdx.x % (L_ / TI_)) * TI_;
    const int lane = t & 31;
    const int wid  = t >> 5;

    // --- staging: coalesced read of whole batch coords -> padded transpose ---
    const float* Xb = X + (size_t)b * L_ * C_ * 3;
    #pragma unroll
    for (int k = 0; k < 42; k++) {
        int idx = k * L_ + t;
        int j   = idx / 42;
        int r   = idx - j * 42;
        sm.f.sraw[r * 129 + j] = Xb[idx];
    }
    sm.f.sS[t]   = S[b * L_ + t];
    sm.f.sSeg[t] = seg[b * L_ + t];
    __syncthreads();

    // --- per-column coords packed (pairs of atoms), poisoned sq norms ---
    u64t y0p[C_/2], y1p[C_/2], y2p[C_/2], sjp[C_/2];
    const int* apRow = AP + ((size_t)b * L_ + t) * C_;
    #pragma unroll
    for (int c = 0; c < C_; c++) {
        float a0 = sm.f.sraw[(3*c + 0) * 129 + t];
        float a1 = sm.f.sraw[(3*c + 1) * 129 + t];
        float a2 = sm.f.sraw[(3*c + 2) * 129 + t];
        float sq = (a0*a0 + a1*a1) + a2*a2;
        sq = (apRow[c] != 0) ? sq : POISON;
        sm.f.ssq[c * L_ + t] = sq;
        int p = c >> 1;
        if ((c & 1) == 0) { y0p[p] = pack2(a0, 0.f); y1p[p] = pack2(a1, 0.f); y2p[p] = pack2(a2, 0.f); sjp[p] = pack2(sq, 0.f); }
        else {
            float l0, h0;
            unpack2(y0p[p], l0, h0); y0p[p] = pack2(l0, a0);
            unpack2(y1p[p], l0, h0); y1p[p] = pack2(l0, a1);
            unpack2(y2p[p], l0, h0); y2p[p] = pack2(l0, a2);
            unpack2(sjp[p], l0, h0); sjp[p] = pack2(l0, sq);
        }
    }
    __syncthreads();

    const u64t negtwo = pack2(-2.0f, -2.0f);

    // --- distance rows ---
    #pragma unroll
    for (int ii = 0; ii < TI_; ii++) {
        int i = i0 + ii;
        float best0 = FLT_MAX, best1 = FLT_MAX;
        #pragma unroll
        for (int c = 0; c < C_; c++) {
            float xi0 = sm.f.sraw[(3*c + 0) * 129 + i];   // conflict-free broadcast
            float xi1 = sm.f.sraw[(3*c + 1) * 129 + i];
            float xi2 = sm.f.sraw[(3*c + 2) * 129 + i];
            float sqc = sm.f.ssq[c * L_ + i];
            u64t xi0p = pack2(xi0, xi0);
            u64t xi1p = pack2(xi1, xi1);
            u64t xi2p = pack2(xi2, xi2);
            u64t sqcp = pack2(sqc, sqc);
            #pragma unroll
            for (int p = 0; p < C_/2; p++) {
                // dot = (xi0*y0 + xi1*y1) + xi2*y2   (mul, fma, fma — same as scalar)
                u64t dot = fma2(xi2p, y2p[p], fma2(xi1p, y1p[p], mul2(xi0p, y0p[p])));
                // d2 = (sqc + sj) - 2*dot            (add, fma — same as scalar)
                u64t d2  = fma2(dot, negtwo, add2(sqcp, sjp[p]));
                float lo, hi;
                unpack2(d2, lo, hi);
                best0 = fminf(best0, lo);
                best1 = fminf(best1, hi);
            }
        }
        float best = fminf(best0, best1);
        sm.f.sdist[ii * L_ + t] = sqrtf(fmaxf(best, 0.0f));
    }

    // --- adj rows ---
    {
        bool gj = is_glob(sm.f.sS[t]);
        int  segj = sm.f.sSeg[t];
        #pragma unroll
        for (int ii = 0; ii < TI_; ii++) {
            int i = i0 + ii;
            bool gi = is_glob(sm.f.sS[i]);
            bool same = (sm.f.sSeg[i] == segj);
            bool ns   = (i != t);
            bool gn = same && (gi || gj) && ns;
            bool gg = gi && gj && ns;
            int  d  = i - t; if (d < 0) d = -d;
            bool sme = (d == 1) && !gi && !gj && (sm.f.sSeg[i] != 1);
            out[OFF_ADJ + ((unsigned)(b * L_ + i)) * L_ + t] = (gn || gg || sme) ? 1.0f : 0.0f;
        }
    }
    __syncthreads();

    // --- knn: 2*TI_ warp tasks over smem dist rows ---
    for (int tt = wid; tt < 2 * TI_; tt += 4) {
        int ii   = tt >> 1;
        int type = tt & 1;                  // 0 = ctx (inner), 1 = inter (outer)
        int i    = i0 + ii;
        int r    = b * L_ + i;
        bool gi  = is_glob(sm.f.sS[i]);
        int  si  = sm.f.sSeg[i];

        float v[4];
        #pragma unroll
        for (int s2 = 0; s2 < 4; s2++) {
            int j = lane + 32 * s2;
            bool gj   = is_glob(sm.f.sS[j]);
            bool same = (sm.f.sSeg[j] == si);
            bool m;
            if (type == 0) m = same && !gi && !gj && (j != i);
            else           m = !same && !gi && !gj;
            v[s2] = m ? sm.f.sdist[ii * L_ + j] : BIGF;
        }

        unsigned offK = type ? OFF_INT_KNN   : OFF_CTX_KNN;
        unsigned offV = type ? OFF_INT_VALID : OFF_CTX_VALID;

        for (int k = 0; k < K_; k++) {
            float bv = v[0]; int bj = lane;
            #pragma unroll
            for (int s2 = 1; s2 < 4; s2++) {
                int j = lane + 32 * s2;
                if (v[s2] < bv) { bv = v[s2]; bj = j; }  // j increases, '<' keeps smallest index
            }
            #pragma unroll
            for (int off = 16; off; off >>= 1) {
                float ov = __shfl_xor_sync(0xffffffffu, bv, off);
                int   oj = __shfl_xor_sync(0xffffffffu, bj, off);
                if (ov < bv || (ov == bv && oj < bj)) { bv = ov; bj = oj; }
            }
            if (lane == (bj & 31)) v[bj >> 5] = POISON;
            if (lane == 0) {
                bool valid = bv < BIGF;
                out[offK + (unsigned)r * K_ + k]            = valid ? (float)r           : -1.0f;
                out[offK + KNN_ROWS + (unsigned)r * K_ + k] = valid ? (float)(b*L_ + bj) : -1.0f;
                out[offV + (unsigned)r * K_ + k]            = valid ? 1.0f : 0.0f;
            }
        }
    }
}

// ---------------------------------------------------------------------------
extern "C" void kernel_launch(void* const* d_in, const int* in_sizes, int n_in,
                              void* d_out, int out_size)
{
    const int*   S   = (const int*)  d_in[0];
    const int*   RP  = (const int*)  d_in[1];
    const int*   A   = (const int*)  d_in[2];
    const int*   AP  = (const int*)  d_in[3];
    const float* X   = (const float*)d_in[4];
    const int*   seg = (const int*)  d_in[5];
    const float* re  = (const float*)d_in[6];
    const float* ae  = (const float*)d_in[7];
    const float* ape = (const float*)d_in[8];
    float* out = (float*)d_out;

    mono_kernel<<<FUSED_BLOCKS + N_, L_>>>(X, AP, S, seg, RP, A, re, ae, ape, out);
}

// round 4
// speedup vs baseline: 2.1634x; 1.0011x over previous
#include <cuda_runtime.h>
#include <float.h>

// Problem constants (fixed by setup_inputs)
#define B_   16
#define L_   128
#define N_   (B_*L_)      // 2048
#define C_   14
#define E_   256
#define K_   9
#define TI_  2            // i-rows per fused block
#define NT_  256          // threads per block (2 atom-groups x 128 columns)
#define FUSED_BLOCKS (B_ * (L_ / TI_))   // 1024
#define BIGF 1e10f
#define POISON 3.0e38f

// Output layout (float32, outputs flattened + concatenated in reference order)
#define OFF_H          0u
#define OFF_CTX_KNN    1048576u
#define OFF_CTX_VALID  1085440u
#define OFF_ADJ        1103872u
#define OFF_INT_KNN    1366016u
#define OFF_INT_VALID  1402880u
#define KNN_ROWS       (N_*K_)   // 18432

__device__ __forceinline__ bool is_glob(int s) { return (s == 21) | (s == 22) | (s == 23); }

// ---- packed f32x2 helpers (per-half IEEE identical to scalar sequence) ----
typedef unsigned long long u64t;
__device__ __forceinline__ u64t pack2(float lo, float hi) {
    u64t r; asm("mov.b64 %0, {%1,%2};" : "=l"(r) : "f"(lo), "f"(hi)); return r;
}
__device__ __forceinline__ void unpack2(u64t p, float& lo, float& hi) {
    asm("mov.b64 {%0,%1}, %2;" : "=f"(lo), "=f"(hi) : "l"(p));
}
__device__ __forceinline__ u64t mul2(u64t a, u64t b) {
    u64t r; asm("mul.rn.f32x2 %0, %1, %2;" : "=l"(r) : "l"(a), "l"(b)); return r;
}
__device__ __forceinline__ u64t add2(u64t a, u64t b) {
    u64t r; asm("add.rn.f32x2 %0, %1, %2;" : "=l"(r) : "l"(a), "l"(b)); return r;
}
__device__ __forceinline__ u64t fma2(u64t a, u64t b, u64t c) {
    u64t r; asm("fma.rn.f32x2 %0, %1, %2, %3;" : "=l"(r) : "l"(a), "l"(b), "l"(c)); return r;
}

struct SmemFused {
    u64t  sdup[TI_ * C_ * 4];     // duplicated {v,v} broadcast operands: x0,x1,x2,sq per (ii,c)
    float sraw[42 * 129];         // [r=c*3+d][j], pitch 129 (transpose pad)
    float ssq [C_ * L_];          // [c][j], poisoned if atom invalid
    float spart[2][TI_][L_];      // partial min d2 per atom-group
    float sdist[TI_ * L_];
    int   sS[L_], sSeg[L_];
};
struct SmemEmbed {
    int sA[C_], sAP[C_];
};
union SmemAll { SmemFused f; SmemEmbed e; };

// ---------------------------------------------------------------------------
// Single kernel; blockIdx < FUSED_BLOCKS -> dist+knn+adj, else -> embed.
// ---------------------------------------------------------------------------
__global__ void __launch_bounds__(NT_) mono_kernel(
        const float* __restrict__ X, const int* __restrict__ AP,
        const int* __restrict__ S, const int* __restrict__ seg,
        const int* __restrict__ RP, const int* __restrict__ A,
        const float* __restrict__ res_e, const float* __restrict__ atom_e,
        const float* __restrict__ atom_pe,
        float* __restrict__ out)
{
    __shared__ SmemAll sm;
    const int t = threadIdx.x;

    if (blockIdx.x >= FUSED_BLOCKS) {
        // ================= EMBED: one residue, 256 threads = 256 channels ===
        const int n = blockIdx.x - FUSED_BLOCKS;
        if (t < C_) { sm.e.sA[t] = A[n*C_ + t]; sm.e.sAP[t] = AP[n*C_ + t]; }
        __syncthreads();
        int cnt = 0;
        #pragma unroll
        for (int c = 0; c < C_; c++) cnt += (sm.e.sAP[c] != 0);
        float den = (float)cnt + 1e-10f;

        int   s  = S[n];
        float rp = (float)RP[n];
        int   e  = t;
        int   i2 = e >> 1;
        float inv = exp2f(-(float)i2 * (13.287712379549449f / 128.0f));
        float ang = rp * inv;
        float pos = (e & 1) ? cosf(ang) : sinf(ang);
        out[OFF_H + (unsigned)n * 512u + e] = res_e[s * E_ + e] + pos;

        float acc = 0.0f;
        #pragma unroll
        for (int c = 0; c < C_; c++) {
            int ap = sm.e.sAP[c];
            if (ap != 0) acc += atom_e[sm.e.sA[c] * E_ + e] + atom_pe[ap * E_ + e];
        }
        out[OFF_H + (unsigned)n * 512u + 256u + e] = acc / den;
        return;
    }

    // ================= FUSED dist + knn + adj ===============================
    const int b  = blockIdx.x / (L_ / TI_);
    const int i0 = (blockIdx.x % (L_ / TI_)) * TI_;
    const int g  = t >> 7;          // atom-group: 0 -> atoms 0..7, 1 -> atoms 8..13
    const int j  = t & 127;         // column
    const int lane = t & 31;
    const int wid  = t >> 5;

    // --- staging: coalesced read of whole batch coords -> padded transpose ---
    const float* Xb = X + (size_t)b * L_ * C_ * 3;
    #pragma unroll
    for (int k = 0; k < 21; k++) {
        int idx = k * NT_ + t;               // 21*256 = 5376 = L_*C_*3
        int jj  = idx / 42;
        int r   = idx - jj * 42;
        sm.f.sraw[r * 129 + jj] = Xb[idx];
    }
    if (t < L_) {
        sm.f.sS[t]   = S[b * L_ + t];
        sm.f.sSeg[t] = seg[b * L_ + t];
    }
    __syncthreads();

    // --- per (group, column): own 4 atom-pairs into packed registers; ssq to smem ---
    u64t y0p[4], y1p[4], y2p[4], sjp[4];
    {
        const int cbase = g * 8;
        const int* apRow = AP + ((size_t)b * L_ + j) * C_;
        #pragma unroll
        for (int p = 0; p < 4; p++) {
            float a0l=0.f,a1l=0.f,a2l=0.f,sql=POISON;
            float a0h=0.f,a1h=0.f,a2h=0.f,sqh=POISON;
            int c0 = cbase + 2*p, c1 = c0 + 1;
            if (c0 < C_) {
                a0l = sm.f.sraw[(3*c0+0)*129 + j];
                a1l = sm.f.sraw[(3*c0+1)*129 + j];
                a2l = sm.f.sraw[(3*c0+2)*129 + j];
                float sq = (a0l*a0l + a1l*a1l) + a2l*a2l;
                sql = (apRow[c0] != 0) ? sq : POISON;
                sm.f.ssq[c0 * L_ + j] = sql;
            }
            if (c1 < C_) {
                a0h = sm.f.sraw[(3*c1+0)*129 + j];
                a1h = sm.f.sraw[(3*c1+1)*129 + j];
                a2h = sm.f.sraw[(3*c1+2)*129 + j];
                float sq = (a0h*a0h + a1h*a1h) + a2h*a2h;
                sqh = (apRow[c1] != 0) ? sq : POISON;
                sm.f.ssq[c1 * L_ + j] = sqh;
            }
            y0p[p] = pack2(a0l, a0h);
            y1p[p] = pack2(a1l, a1h);
            y2p[p] = pack2(a2l, a2h);
            sjp[p] = pack2(sql, sqh);
        }
    }
    __syncthreads();

    // --- build duplicated broadcast operands for the TI_ i-rows ---
    if (t < TI_ * C_) {
        int ii = t / C_, c = t % C_;
        int i  = i0 + ii;
        float v0 = sm.f.sraw[(3*c+0)*129 + i];
        float v1 = sm.f.sraw[(3*c+1)*129 + i];
        float v2 = sm.f.sraw[(3*c+2)*129 + i];
        float sq = sm.f.ssq[c * L_ + i];
        u64t* d = &sm.f.sdup[(ii * C_ + c) * 4];
        d[0] = pack2(v0, v0); d[1] = pack2(v1, v1);
        d[2] = pack2(v2, v2); d[3] = pack2(sq, sq);
    }
    __syncthreads();

    // --- hot loop: partial min over this group's atom pairs ---
    const u64t negtwo = pack2(-2.0f, -2.0f);
    #pragma unroll
    for (int ii = 0; ii < TI_; ii++) {
        float best0 = FLT_MAX, best1 = FLT_MAX;
        const u64t* dup = &sm.f.sdup[ii * C_ * 4];
        #pragma unroll
        for (int c = 0; c < C_; c++) {
            u64t xi0p = dup[c*4 + 0];
            u64t xi1p = dup[c*4 + 1];
            u64t xi2p = dup[c*4 + 2];
            u64t sqcp = dup[c*4 + 3];
            #pragma unroll
            for (int p = 0; p < 4; p++) {
                u64t dot = fma2(xi2p, y2p[p], fma2(xi1p, y1p[p], mul2(xi0p, y0p[p])));
                u64t d2  = fma2(dot, negtwo, add2(sqcp, sjp[p]));
                float lo, hi;
                unpack2(d2, lo, hi);
                if (p & 1) { best1 = fminf(best1, lo); best1 = fminf(best1, hi); }
                else       { best0 = fminf(best0, lo); best0 = fminf(best0, hi); }
            }
        }
        sm.f.spart[g][ii][j] = fminf(best0, best1);
    }

    // --- adj row write: thread (g, j) handles row i0+g (TI_ == 2) ---
    {
        int i = i0 + g;
        bool gi = is_glob(sm.f.sS[i]);
        bool gj = is_glob(sm.f.sS[j]);
        bool same = (sm.f.sSeg[i] == sm.f.sSeg[j]);
        bool ns   = (i != j);
        bool gn = same && (gi || gj) && ns;
        bool gg = gi && gj && ns;
        int  d  = i - j; if (d < 0) d = -d;
        bool sme = (d == 1) && !gi && !gj && (sm.f.sSeg[i] != 1);
        out[OFF_ADJ + ((unsigned)(b * L_ + i)) * L_ + j] = (gn || gg || sme) ? 1.0f : 0.0f;
    }
    __syncthreads();

    // --- combine partials, sqrt -> dist rows ---
    if (t < L_) {
        #pragma unroll
        for (int ii = 0; ii < TI_; ii++) {
            float d2 = fminf(sm.f.spart[0][ii][t], sm.f.spart[1][ii][t]);
            sm.f.sdist[ii * L_ + t] = sqrtf(fmaxf(d2, 0.0f));
        }
    }
    __syncthreads();

    // --- knn: 2*TI_ = 4 warp tasks (warps 0..3) ---
    if (wid < 2 * TI_) {
        int ii   = wid >> 1;
        int type = wid & 1;                  // 0 = ctx (inner), 1 = inter (outer)
        int i    = i0 + ii;
        int r    = b * L_ + i;
        bool gi  = is_glob(sm.f.sS[i]);
        int  si  = sm.f.sSeg[i];

        float v[4];
        #pragma unroll
        for (int s2 = 0; s2 < 4; s2++) {
            int jj = lane + 32 * s2;
            bool gj   = is_glob(sm.f.sS[jj]);
            bool same = (sm.f.sSeg[jj] == si);
            bool m;
            if (type == 0) m = same && !gi && !gj && (jj != i);
            else           m = !same && !gi && !gj;
            v[s2] = m ? sm.f.sdist[ii * L_ + jj] : BIGF;
        }

        unsigned offK = type ? OFF_INT_KNN   : OFF_CTX_KNN;
        unsigned offV = type ? OFF_INT_VALID : OFF_CTX_VALID;

        for (int k = 0; k < K_; k++) {
            float bv = v[0]; int bj = lane;
            #pragma unroll
            for (int s2 = 1; s2 < 4; s2++) {
                int jj = lane + 32 * s2;
                if (v[s2] < bv) { bv = v[s2]; bj = jj; }   // jj increases, '<' keeps smallest index
            }
            #pragma unroll
            for (int off = 16; off; off >>= 1) {
                float ov = __shfl_xor_sync(0xffffffffu, bv, off);
                int   oj = __shfl_xor_sync(0xffffffffu, bj, off);
                if (ov < bv || (ov == bv && oj < bj)) { bv = ov; bj = oj; }
            }
            if (lane == (bj & 31)) v[bj >> 5] = POISON;
            if (lane == 0) {
                bool valid = bv < BIGF;
                out[offK + (unsigned)r * K_ + k]            = valid ? (float)r           : -1.0f;
                out[offK + KNN_ROWS + (unsigned)r * K_ + k] = valid ? (float)(b*L_ + bj) : -1.0f;
                out[offV + (unsigned)r * K_ + k]            = valid ? 1.0f : 0.0f;
            }
        }
    }
}

// ---------------------------------------------------------------------------
extern "C" void kernel_launch(void* const* d_in, const int* in_sizes, int n_in,
                              void* d_out, int out_size)
{
    const int*   S   = (const int*)  d_in[0];
    const int*   RP  = (const int*)  d_in[1];
    const int*   A   = (const int*)  d_in[2];
    const int*   AP  = (const int*)  d_in[3];
    const float* X   = (const float*)d_in[4];
    const int*   seg = (const int*)  d_in[5];
    const float* re  = (const float*)d_in[6];
    const float* ae  = (const float*)d_in[7];
    const float* ape = (const float*)d_in[8];
    float* out = (float*)d_out;

    mono_kernel<<<FUSED_BLOCKS + N_, NT_>>>(X, AP, S, seg, RP, A, re, ae, ape, out);
}

// round 6
// speedup vs baseline: 2.3228x; 1.0737x over previous
#include <cuda_runtime.h>
#include <float.h>

// Problem constants (fixed by setup_inputs)
#define B_   16
#define L_   128
#define N_   (B_*L_)      // 2048
#define C_   14
#define E_   256
#define K_   9
#define TI_  4            // i-rows per fused block
#define NT_  256          // threads per block (2 atom-groups x 128 columns)
#define FUSED_BLOCKS (B_ * (L_ / TI_))   // 512
#define BIGF 1e10f
#define POISON 3.0e38f

// Output layout (float32, outputs flattened + concatenated in reference order)
#define OFF_H          0u
#define OFF_CTX_KNN    1048576u
#define OFF_CTX_VALID  1085440u
#define OFF_ADJ        1103872u
#define OFF_INT_KNN    1366016u
#define OFF_INT_VALID  1402880u
#define KNN_ROWS       (N_*K_)   // 18432

__device__ __forceinline__ bool is_glob(int s) { return (s == 21) | (s == 22) | (s == 23); }

// ---- packed f32x2 helpers (per-half IEEE identical to scalar sequence) ----
typedef unsigned long long u64t;
__device__ __forceinline__ u64t pack2(float lo, float hi) {
    u64t r; asm("mov.b64 %0, {%1,%2};" : "=l"(r) : "f"(lo), "f"(hi)); return r;
}
__device__ __forceinline__ void unpack2(u64t p, float& lo, float& hi) {
    asm("mov.b64 {%0,%1}, %2;" : "=f"(lo), "=f"(hi) : "l"(p));
}
__device__ __forceinline__ u64t mul2(u64t a, u64t b) {
    u64t r; asm("mul.rn.f32x2 %0, %1, %2;" : "=l"(r) : "l"(a), "l"(b)); return r;
}
__device__ __forceinline__ u64t add2(u64t a, u64t b) {
    u64t r; asm("add.rn.f32x2 %0, %1, %2;" : "=l"(r) : "l"(a), "l"(b)); return r;
}
__device__ __forceinline__ u64t fma2(u64t a, u64t b, u64t c) {
    u64t r; asm("fma.rn.f32x2 %0, %1, %2, %3;" : "=l"(r) : "l"(a), "l"(b), "l"(c)); return r;
}

struct SmemFused {
    u64t  sdup[TI_ * C_ * 4];     // duplicated {v,v} broadcast operands: x0,x1,x2,sq per (ii,c)
    float sraw[42 * 129];         // [r=c*3+d][j], pitch 129 (transpose pad)
    float ssq [C_ * L_];          // [c][j], poisoned if atom invalid
    float spart[2][TI_][L_];      // partial min d2 per atom-group
    int   sS[L_], sSeg[L_];
};
struct SmemEmbed {
    int sA[C_], sAP[C_];
};
union SmemAll { SmemFused f; SmemEmbed e; };

// ---------------------------------------------------------------------------
// Single kernel; blockIdx < FUSED_BLOCKS -> dist+knn+adj, else -> embed.
// ---------------------------------------------------------------------------
__global__ void __launch_bounds__(NT_, 4) mono_kernel(
        const float* __restrict__ X, const int* __restrict__ AP,
        const int* __restrict__ S, const int* __restrict__ seg,
        const int* __restrict__ RP, const int* __restrict__ A,
        const float* __restrict__ res_e, const float* __restrict__ atom_e,
        const float* __restrict__ atom_pe,
        float* __restrict__ out)
{
    __shared__ SmemAll sm;
    const int t = threadIdx.x;

    if (blockIdx.x >= FUSED_BLOCKS) {
        // ================= EMBED: one residue, 256 threads = 256 channels ===
        const int n = blockIdx.x - FUSED_BLOCKS;
        if (t < C_) { sm.e.sA[t] = A[n*C_ + t]; sm.e.sAP[t] = AP[n*C_ + t]; }
        __syncthreads();
        int cnt = 0;
        #pragma unroll
        for (int c = 0; c < C_; c++) cnt += (sm.e.sAP[c] != 0);
        float den = (float)cnt + 1e-10f;

        int   s  = S[n];
        float rp = (float)RP[n];
        int   e  = t;
        int   i2 = e >> 1;
        float inv = exp2f(-(float)i2 * (13.287712379549449f / 128.0f));
        float ang = rp * inv;
        float pos = (e & 1) ? cosf(ang) : sinf(ang);
        out[OFF_H + (unsigned)n * 512u + e] = res_e[s * E_ + e] + pos;

        float acc = 0.0f;
        #pragma unroll
        for (int c = 0; c < C_; c++) {
            int ap = sm.e.sAP[c];
            if (ap != 0) acc += atom_e[sm.e.sA[c] * E_ + e] + atom_pe[ap * E_ + e];
        }
        out[OFF_H + (unsigned)n * 512u + 256u + e] = acc / den;
        return;
    }

    // ================= FUSED dist + knn + adj ===============================
    const int b  = blockIdx.x / (L_ / TI_);
    const int i0 = (blockIdx.x % (L_ / TI_)) * TI_;
    const int g  = t >> 7;          // atom-group: 0 -> atoms 0..7, 1 -> atoms 8..13
    const int j  = t & 127;         // column
    const int lane = t & 31;
    const int wid  = t >> 5;

    // --- staging: coalesced read of whole batch coords -> padded transpose ---
    const float* Xb = X + (size_t)b * L_ * C_ * 3;
    #pragma unroll
    for (int k = 0; k < 21; k++) {
        int idx = k * NT_ + t;               // 21*256 = 5376 = L_*C_*3
        int jj  = idx / 42;
        int r   = idx - jj * 42;
        sm.f.sraw[r * 129 + jj] = Xb[idx];
    }
    if (t < L_) {
        sm.f.sS[t]   = S[b * L_ + t];
        sm.f.sSeg[t] = seg[b * L_ + t];
    }
    __syncthreads();

    // --- per (group, column): own 4 atom-pairs into packed registers; ssq to smem ---
    u64t y0p[4], y1p[4], y2p[4], sjp[4];
    {
        const int cbase = g * 8;
        const int* apRow = AP + ((size_t)b * L_ + j) * C_;
        #pragma unroll
        for (int p = 0; p < 4; p++) {
            float a0l=0.f,a1l=0.f,a2l=0.f,sql=POISON;
            float a0h=0.f,a1h=0.f,a2h=0.f,sqh=POISON;
            int c0 = cbase + 2*p, c1 = c0 + 1;
            if (c0 < C_) {
                a0l = sm.f.sraw[(3*c0+0)*129 + j];
                a1l = sm.f.sraw[(3*c0+1)*129 + j];
                a2l = sm.f.sraw[(3*c0+2)*129 + j];
                float sq = (a0l*a0l + a1l*a1l) + a2l*a2l;
                sql = (apRow[c0] != 0) ? sq : POISON;
                sm.f.ssq[c0 * L_ + j] = sql;
            }
            if (c1 < C_) {
                a0h = sm.f.sraw[(3*c1+0)*129 + j];
                a1h = sm.f.sraw[(3*c1+1)*129 + j];
                a2h = sm.f.sraw[(3*c1+2)*129 + j];
                float sq = (a0h*a0h + a1h*a1h) + a2h*a2h;
                sqh = (apRow[c1] != 0) ? sq : POISON;
                sm.f.ssq[c1 * L_ + j] = sqh;
            }
            y0p[p] = pack2(a0l, a0h);
            y1p[p] = pack2(a1l, a1h);
            y2p[p] = pack2(a2l, a2h);
            sjp[p] = pack2(sql, sqh);
        }
    }
    __syncthreads();

    // --- build duplicated broadcast operands for the TI_ i-rows ---
    if (t < TI_ * C_) {
        int ii = t / C_, c = t % C_;
        int i  = i0 + ii;
        float v0 = sm.f.sraw[(3*c+0)*129 + i];
        float v1 = sm.f.sraw[(3*c+1)*129 + i];
        float v2 = sm.f.sraw[(3*c+2)*129 + i];
        float sq = sm.f.ssq[c * L_ + i];
        u64t* d = &sm.f.sdup[(ii * C_ + c) * 4];
        d[0] = pack2(v0, v0); d[1] = pack2(v1, v1);
        d[2] = pack2(v2, v2); d[3] = pack2(sq, sq);
    }
    __syncthreads();

    // --- hot loop: partial min over this group's atom pairs ---
    const u64t negtwo = pack2(-2.0f, -2.0f);
    #pragma unroll 2
    for (int ii = 0; ii < TI_; ii++) {
        float b0 = FLT_MAX, b1 = FLT_MAX, b2 = FLT_MAX, b3 = FLT_MAX;
        const u64t* dup = &sm.f.sdup[ii * C_ * 4];
        #pragma unroll
        for (int c = 0; c < C_; c++) {
            u64t xi0p = dup[c*4 + 0];
            u64t xi1p = dup[c*4 + 1];
            u64t xi2p = dup[c*4 + 2];
            u64t sqcp = dup[c*4 + 3];
            #pragma unroll
            for (int p = 0; p < 4; p += 2) {
                {
                    u64t dot = fma2(xi2p, y2p[p], fma2(xi1p, y1p[p], mul2(xi0p, y0p[p])));
                    u64t d2  = fma2(dot, negtwo, add2(sqcp, sjp[p]));
                    float lo, hi;
                    unpack2(d2, lo, hi);          // register aliasing, no SASS op
                    b0 = fminf(b0, lo);
                    b1 = fminf(b1, hi);
                }
                {
                    u64t dot = fma2(xi2p, y2p[p+1], fma2(xi1p, y1p[p+1], mul2(xi0p, y0p[p+1])));
                    u64t d2  = fma2(dot, negtwo, add2(sqcp, sjp[p+1]));
                    float lo, hi;
                    unpack2(d2, lo, hi);
                    b2 = fminf(b2, lo);
                    b3 = fminf(b3, hi);
                }
            }
        }
        sm.f.spart[g][ii][j] = fminf(fminf(b0, b1), fminf(b2, b3));
    }

    // --- adj rows: thread (g, j) handles rows i0 + 2g, i0 + 2g + 1 ---
    {
        bool gj = is_glob(sm.f.sS[j]);
        int  segj = sm.f.sSeg[j];
        #pragma unroll
        for (int r2 = 0; r2 < 2; r2++) {
            int i = i0 + g * 2 + r2;
            bool gi = is_glob(sm.f.sS[i]);
            bool same = (sm.f.sSeg[i] == segj);
            bool ns   = (i != j);
            bool gn = same && (gi || gj) && ns;
            bool gg = gi && gj && ns;
            int  d  = i - j; if (d < 0) d = -d;
            bool sme = (d == 1) && !gi && !gj && (sm.f.sSeg[i] != 1);
            out[OFF_ADJ + ((unsigned)(b * L_ + i)) * L_ + j] = (gn || gg || sme) ? 1.0f : 0.0f;
        }
    }
    __syncthreads();

    // --- knn: 2*TI_ = 8 warp tasks (all 8 warps busy) ---
    {
        int ii   = wid >> 1;
        int type = wid & 1;                  // 0 = ctx (inner), 1 = inter (outer)
        int i    = i0 + ii;
        int r    = b * L_ + i;
        bool gi  = is_glob(sm.f.sS[i]);
        int  si  = sm.f.sSeg[i];

        float v[4];
        #pragma unroll
        for (int s2 = 0; s2 < 4; s2++) {
            int jj = lane + 32 * s2;
            bool gj   = is_glob(sm.f.sS[jj]);
            bool same = (sm.f.sSeg[jj] == si);
            bool m;
            if (type == 0) m = same && !gi && !gj && (jj != i);
            else           m = !same && !gi && !gj;
            float d2 = fminf(sm.f.spart[0][ii][jj], sm.f.spart[1][ii][jj]);
            v[s2] = m ? sqrtf(fmaxf(d2, 0.0f)) : BIGF;
        }

        unsigned offK = type ? OFF_INT_KNN   : OFF_CTX_KNN;
        unsigned offV = type ? OFF_INT_VALID : OFF_CTX_VALID;

        for (int k = 0; k < K_; k++) {
            float bv = v[0]; int bj = lane;
            #pragma unroll
            for (int s2 = 1; s2 < 4; s2++) {
                int jj = lane + 32 * s2;
                if (v[s2] < bv) { bv = v[s2]; bj = jj; }   // jj increases, '<' keeps smallest index
            }
            #pragma unroll
            for (int off = 16; off; off >>= 1) {
                float ov = __shfl_xor_sync(0xffffffffu, bv, off);
                int   oj = __shfl_xor_sync(0xffffffffu, bj, off);
                if (ov < bv || (ov == bv && oj < bj)) { bv = ov; bj = oj; }
            }
            if (lane == (bj & 31)) v[bj >> 5] = POISON;
            if (lane == 0) {
                bool valid = bv < BIGF;
                out[offK + (unsigned)r * K_ + k]            = valid ? (float)r           : -1.0f;
                out[offK + KNN_ROWS + (unsigned)r * K_ + k] = valid ? (float)(b*L_ + bj) : -1.0f;
                out[offV + (unsigned)r * K_ + k]            = valid ? 1.0f : 0.0f;
            }
        }
    }
}

// ---------------------------------------------------------------------------
extern "C" void kernel_launch(void* const* d_in, const int* in_sizes, int n_in,
                              void* d_out, int out_size)
{
    const int*   S   = (const int*)  d_in[0];
    const int*   RP  = (const int*)  d_in[1];
    const int*   A   = (const int*)  d_in[2];
    const int*   AP  = (const int*)  d_in[3];
    const float* X   = (const float*)d_in[4];
    const int*   seg = (const int*)  d_in[5];
    const float* re  = (const float*)d_in[6];
    const float* ae  = (const float*)d_in[7];
    const float* ape = (const float*)d_in[8];
    float* out = (float*)d_out;

    mono_kernel<<<FUSED_BLOCKS + N_, NT_>>>(X, AP, S, seg, RP, A, re, ae, ape, out);
}